// round 3
// baseline (speedup 1.0000x reference)
#include <cuda_runtime.h>
#include <cuda_fp16.h>

// Problem constants (fixed by dataset)
#define BB 64
#define NN 50000
#define EE 1600000
#define LL 20
#define BN_EPS 1e-5f

#define SCAN_BLK 1024
#define NBLOCKS_SCAN ((NN + SCAN_BLK - 1) / SCAN_BLK)   // 49

// ---------------- scratch (static device globals; no allocation) ----------------
__device__ __half g_xT[(size_t)NN * BB];     // x transposed [N, B] fp16   6.4 MB
__device__ float  g_xhT[(size_t)NN * BB];    // x_hat transposed [N, B]   12.8 MB
__device__ int    g_counts[NN];
__device__ int    g_offsets[NN];             // exclusive scan; mutated to "ends"
__device__ int    g_blocksum[NBLOCKS_SCAN];
__device__ int    g_blockoff[NBLOCKS_SCAN];
__device__ int4   g_csr[EE];                 // {src, alpha_bits, bias_bits, 0}

// ---------------- kernels ----------------

__global__ void zero_kernel() {
    int i = blockIdx.x * blockDim.x + threadIdx.x;
    if (i < NN) g_counts[i] = 0;
}

// x [B, N] fp32 -> g_xT [N, B] fp16 (half2-packed rows)
__global__ void transpose_kernel(const float* __restrict__ x) {
    __shared__ float tile[64][33];
    const int n0 = blockIdx.x * 32;
    int n = n0 + threadIdx.x;
    #pragma unroll
    for (int h = 0; h < 2; h++) {
        int b = h * 32 + threadIdx.y;
        if (n < NN) tile[b][threadIdx.x] = x[(size_t)b * NN + n];
    }
    __syncthreads();
    int nn = n0 + threadIdx.y;
    if (nn < NN) {
        float lo = tile[2 * threadIdx.x    ][threadIdx.y];
        float hi = tile[2 * threadIdx.x + 1][threadIdx.y];
        ((half2*)g_xT)[(size_t)nn * 32 + threadIdx.x] = __floats2half2_rn(lo, hi);
    }
}

__global__ void init_pred_kernel(const float* __restrict__ b_lin, float* __restrict__ pred) {
    int i = blockIdx.x * blockDim.x + threadIdx.x;
    if (i < BB * LL) pred[i] = b_lin[i % LL];
}

// histogram of dst (4 edges / thread, vectorized)
__global__ void hist_kernel(const int* __restrict__ dst) {
    int i = blockIdx.x * blockDim.x + threadIdx.x;
    if (i < EE / 4) {
        int4 d = ((const int4*)dst)[i];
        atomicAdd(&g_counts[d.x], 1);
        atomicAdd(&g_counts[d.y], 1);
        atomicAdd(&g_counts[d.z], 1);
        atomicAdd(&g_counts[d.w], 1);
    }
}

__device__ __forceinline__ int warp_incl_scan(int v, int lane) {
    #pragma unroll
    for (int off = 1; off < 32; off <<= 1) {
        int t = __shfl_up_sync(0xFFFFFFFFu, v, off);
        if (lane >= off) v += t;
    }
    return v;
}

// phase 1: per-block exclusive scan of counts; emit block totals
__global__ __launch_bounds__(SCAN_BLK) void scan_local_kernel() {
    __shared__ int warp_tot[32];
    int i = blockIdx.x * SCAN_BLK + threadIdx.x;
    int lane = threadIdx.x & 31, wid = threadIdx.x >> 5;
    int v = (i < NN) ? g_counts[i] : 0;
    int incl = warp_incl_scan(v, lane);
    if (lane == 31) warp_tot[wid] = incl;
    __syncthreads();
    if (wid == 0) {
        int w = warp_tot[lane];
        warp_tot[lane] = warp_incl_scan(w, lane) - w;  // exclusive warp offsets
    }
    __syncthreads();
    int excl = warp_tot[wid] + incl - v;
    if (i < NN) g_offsets[i] = excl;
    if (threadIdx.x == SCAN_BLK - 1) g_blocksum[blockIdx.x] = warp_tot[wid] + incl;
}

// phase 2: scan the 49 block totals
__global__ void scan_blocks_kernel() {
    __shared__ int sd[64];
    int tid = threadIdx.x;
    int v = (tid < NBLOCKS_SCAN) ? g_blocksum[tid] : 0;
    sd[tid] = v;
    __syncthreads();
    #pragma unroll
    for (int off = 1; off < 64; off <<= 1) {
        int t = (tid >= off) ? sd[tid - off] : 0;
        __syncthreads();
        sd[tid] += t;
        __syncthreads();
    }
    if (tid < NBLOCKS_SCAN) g_blockoff[tid] = sd[tid] - v;
}

// phase 3: add block offsets
__global__ __launch_bounds__(SCAN_BLK) void scan_add_kernel() {
    int i = blockIdx.x * SCAN_BLK + threadIdx.x;
    if (i < NN) g_offsets[i] += g_blockoff[blockIdx.x];
}

// bucket-scatter 16B edge records (4 edges / thread)
__global__ void scatter_kernel(const int* __restrict__ src, const int* __restrict__ dst,
                               const float* __restrict__ alpha, const float* __restrict__ bias) {
    int i = blockIdx.x * blockDim.x + threadIdx.x;
    if (i < EE / 4) {
        int4   s = ((const int4*)src)[i];
        int4   d = ((const int4*)dst)[i];
        float4 a = ((const float4*)alpha)[i];
        float4 b = ((const float4*)bias)[i];
        int p;
        p = atomicAdd(&g_offsets[d.x], 1);
        g_csr[p] = make_int4(s.x, __float_as_int(a.x), __float_as_int(b.x), 0);
        p = atomicAdd(&g_offsets[d.y], 1);
        g_csr[p] = make_int4(s.y, __float_as_int(a.y), __float_as_int(b.y), 0);
        p = atomicAdd(&g_offsets[d.z], 1);
        g_csr[p] = make_int4(s.z, __float_as_int(a.z), __float_as_int(b.z), 0);
        p = atomicAdd(&g_offsets[d.w], 1);
        g_csr[p] = make_int4(s.w, __float_as_int(a.w), __float_as_int(b.w), 0);
    }
}

__device__ __forceinline__ float warp_sum(float v) {
    #pragma unroll
    for (int m = 16; m; m >>= 1) v += __shfl_xor_sync(0xFFFFFFFFu, v, m);
    return v;
}

__device__ __forceinline__ void edge_fma(const int4& r, int lane, float2& acc, float& sb) {
    half2  h  = ((const half2*)g_xT)[(size_t)r.x * 32 + lane];
    float2 vf = __half22float2(h);
    float  a  = __int_as_float(r.y);
    acc.x = fmaf(a, vf.x, acc.x);
    acc.y = fmaf(a, vf.y, acc.y);
    sb += __int_as_float(r.z);
}

// one warp per node: accumulate edges, scatter-mean, tanh, BN; write x_hatT + bn
__global__ __launch_bounds__(1024) void aggregate_kernel(const float* __restrict__ gamma,
                                                         const float* __restrict__ beta,
                                                         float* __restrict__ bn_out) {
    __shared__ float sbn[64][33];
    const int warpId = threadIdx.x >> 5;
    const int lane   = threadIdx.x & 31;
    const int n0 = blockIdx.x * 32;
    const int n  = n0 + warpId;

    if (n < NN) {
        const int end = g_offsets[n];          // mutated to end pointer by scatter
        const int cnt = g_counts[n];
        int j = end - cnt;
        float2 acc = make_float2(0.f, 0.f);
        float  sb  = 0.f;
        for (; j + 4 <= end; j += 4) {
            int4 r0 = __ldg(&g_csr[j]);
            int4 r1 = __ldg(&g_csr[j + 1]);
            int4 r2 = __ldg(&g_csr[j + 2]);
            int4 r3 = __ldg(&g_csr[j + 3]);
            edge_fma(r0, lane, acc, sb);
            edge_fma(r1, lane, acc, sb);
            edge_fma(r2, lane, acc, sb);
            edge_fma(r3, lane, acc, sb);
        }
        for (; j < end; ++j) {
            int4 r = __ldg(&g_csr[j]);
            edge_fma(r, lane, acc, sb);
        }
        float invc = 1.0f / (float)(cnt > 1 ? cnt : 1);
        float2 xh = make_float2((acc.x + sb) * invc, (acc.y + sb) * invc);
        ((float2*)g_xhT)[(size_t)n * 32 + lane] = xh;

        float2 o = make_float2(tanhf(xh.x), tanhf(xh.y));
        float mu  = warp_sum(o.x + o.y) * (1.0f / 64.0f);
        float ex2 = warp_sum(o.x * o.x + o.y * o.y) * (1.0f / 64.0f);
        float var = ex2 - mu * mu;
        float rstd = rsqrtf(var + BN_EPS);
        float g  = gamma[n] * rstd;
        float be = beta[n];
        sbn[2 * lane    ][warpId] = (o.x - mu) * g + be;
        sbn[2 * lane + 1][warpId] = (o.y - mu) * g + be;
    }
    __syncthreads();
    #pragma unroll
    for (int r = threadIdx.x; r < 64 * 32; r += 1024) {
        int b = r >> 5, c = r & 31;
        int nn = n0 + c;
        if (nn < NN) bn_out[(size_t)b * NN + nn] = sbn[b][c];
    }
}

// pred[b,l] += sum_n x_hatT[n,b] * W[l,n]   (128 nodes per block)
__global__ __launch_bounds__(1024) void gemm_kernel(const float* __restrict__ W,
                                                    float* __restrict__ pred) {
    __shared__ float xtile[128 * 64];   // 32 KB
    __shared__ float wtile[LL * 128];   // 10 KB
    const int n0  = blockIdx.x * 128;
    const int rem = min(128, NN - n0);
    const int tid = threadIdx.x;

    for (int idx = tid; idx < 128 * 64; idx += 1024)
        xtile[idx] = (idx < rem * 64) ? g_xhT[(size_t)n0 * 64 + idx] : 0.0f;
    for (int idx = tid; idx < LL * 128; idx += 1024) {
        int l = idx >> 7, nn = idx & 127;
        wtile[idx] = (nn < rem) ? W[(size_t)l * NN + n0 + nn] : 0.0f;
    }
    __syncthreads();

    if (tid < BB / 2 * LL) {           // 640 threads
        int l = tid % LL, b = tid / LL;
        float a0 = 0.f, a1 = 0.f;
        #pragma unroll 8
        for (int nn = 0; nn < 128; ++nn) {
            float w = wtile[l * 128 + nn];
            a0 = fmaf(xtile[nn * 64 + b],      w, a0);
            a1 = fmaf(xtile[nn * 64 + b + 32], w, a1);
        }
        atomicAdd(&pred[b * LL + l],        a0);
        atomicAdd(&pred[(b + 32) * LL + l], a1);
    }
}

// ---------------- launch ----------------
extern "C" void kernel_launch(void* const* d_in, const int* in_sizes, int n_in,
                              void* d_out, int out_size) {
    const float* x     = (const float*)d_in[0];
    const int*   eidx  = (const int*)  d_in[1];
    const float* alpha = (const float*)d_in[2];
    const float* bias  = (const float*)d_in[3];
    const float* W     = (const float*)d_in[4];
    const float* b_lin = (const float*)d_in[5];
    const float* gamma = (const float*)d_in[6];
    const float* beta  = (const float*)d_in[7];

    const int* src = eidx;
    const int* dst = eidx + EE;

    float* pred   = (float*)d_out;              // [B, L] first
    float* bn_out = (float*)d_out + BB * LL;    // then [B, N]

    zero_kernel<<<(NN + 1023) / 1024, 1024>>>();
    {
        dim3 blk(32, 32), grd((NN + 31) / 32, 1);
        transpose_kernel<<<grd, blk>>>(x);
    }
    init_pred_kernel<<<2, 640>>>(b_lin, pred);
    hist_kernel<<<(EE / 4 + 255) / 256, 256>>>(dst);
    scan_local_kernel<<<NBLOCKS_SCAN, SCAN_BLK>>>();
    scan_blocks_kernel<<<1, 64>>>();
    scan_add_kernel<<<NBLOCKS_SCAN, SCAN_BLK>>>();
    scatter_kernel<<<(EE / 4 + 255) / 256, 256>>>(src, dst, alpha, bias);
    aggregate_kernel<<<(NN + 31) / 32, 1024>>>(gamma, beta, bn_out);
    gemm_kernel<<<(NN + 127) / 128, 1024>>>(W, pred);
}